// round 4
// baseline (speedup 1.0000x reference)
#include <cuda_runtime.h>
#include <cuda_bf16.h>

// Problem constants (fixed by the reference setup)
#define Bn 2
#define Pn 1024
#define Hn 128
#define Wn 128
#define NPIX (Hn * Wn)          // 16384
#define TILE 8                  // 8x8 pixel tiles
#define TSX 16                  // tiles per row
#define TSY 16                  // tiles per col
#define NT  (TSX * TSY)         // 256 tiles per camera
#define NTT (Bn * NT)           // 512 tiles total
#define NBLK 128
#define TPB 128

// ---------------------------------------------------------------------------
// Scratch (device globals — no allocations allowed)
// ---------------------------------------------------------------------------
__device__ float4 g_a0[Bn * Pn];    // px, py, conA, conB          (unsorted)
__device__ float4 g_a1[Bn * Pn];    // conC, op, pthr(margin), 1/dep
__device__ float4 g_a2[Bn * Pn];    // rgb0, rgb1, rgb2, pad
__device__ float4 g_bb[Bn * Pn];    // xmin, xmax, ymin, ymax (ellipse AABB)
__device__ float4 g_s0[Bn * Pn];    // depth-sorted versions
__device__ float4 g_s1[Bn * Pn];
__device__ float4 g_s2[Bn * Pn];
__device__ float4 g_sbb[Bn * Pn];
__device__ float  g_depth[Bn * Pn];
__device__ unsigned short g_list[NTT * Pn];   // per-tile depth-ordered lists
__device__ int    g_cnt[NTT];
__device__ unsigned int g_bar[3];   // monotonic barrier counters (never reset)
__device__ unsigned int g_tile_ctr; // render work queue (reset each launch)

// SH constants
#define SH_C0 0.28209479177387814f
#define SH_C1 0.4886025119029199f
#define SH_C2_0 1.0925484305920792f
#define SH_C2_1 (-1.0925484305920792f)
#define SH_C2_2 0.31539156525252005f
#define SH_C2_3 (-1.0925484305920792f)
#define SH_C2_4 0.5462742152960396f
#define SH_C3_0 (-0.5900435899266435f)
#define SH_C3_1 2.890611442640554f
#define SH_C3_2 (-0.4570457994644658f)
#define SH_C3_3 0.3731763325901154f
#define SH_C3_4 (-0.4570457994644658f)
#define SH_C3_5 1.445305721320277f
#define SH_C3_6 (-0.5900435899266435f)

// ---------------------------------------------------------------------------
// Grid-wide barrier. Monotonic ticket counter: every launch adds exactly NBLK
// arrivals per barrier index, so (t/NBLK+1)*NBLK is the release target and no
// reset is ever needed across graph replays. All NBLK blocks are co-resident
// (NBLK=128 <= 148 SMs), so spinning is deadlock-free.
// ---------------------------------------------------------------------------
__device__ __forceinline__ void gbar(int k)
{
    __threadfence();
    __syncthreads();
    if (threadIdx.x == 0) {
        const unsigned t = atomicAdd(&g_bar[k], 1u);
        const unsigned target = (t / NBLK + 1u) * NBLK;
        while (atomicAdd(&g_bar[k], 0u) < target) __nanosleep(64);
        __threadfence();
    }
    __syncthreads();
}

// ---------------------------------------------------------------------------
// Fused kernel: preprocess -> depth sort -> tile bin -> render
// grid = NBLK, block = TPB
// ---------------------------------------------------------------------------
__global__ __launch_bounds__(TPB) void fused_kernel(
    const float* __restrict__ means,      // (P,3)
    const float* __restrict__ opac,       // (P,1)
    const float* __restrict__ scales,     // (P,3)
    const float* __restrict__ rots,       // (P,4)
    const float* __restrict__ sh,         // (P,16,3)
    const float* __restrict__ bg,         // (3)
    const float* __restrict__ viewm,      // (B,4,4) row-major
    const float* __restrict__ projm,      // (B,4,4)
    const float* __restrict__ campos,     // (B,3)
    const float* __restrict__ tanxs,      // (B)
    const float* __restrict__ tanys,      // (B)
    float* __restrict__ out)              // colors | invdepth | radii
{
    const int blk = blockIdx.x;
    const int tid = threadIdx.x;

    __shared__ float sd[Pn];              // phase-2 depth table

    // reset render queue (ordered before any pop by the 3 barriers below)
    if (blk == 0 && tid == 0) g_tile_ctr = 0u;

    // =======================================================================
    // Phase 1: preprocess. 16 gaussians per block => all 128 blocks active.
    // =======================================================================
    if (tid < 16) {
        const int item = blk * 16 + tid;          // 0..2047
        const int b = item >> 10;
        const int p = item & (Pn - 1);
        const float* V  = viewm + b * 16;
        const float* PM = projm + b * 16;
        const float tanx = tanxs[b], tany = tanys[b];

        const float mx = means[p * 3 + 0];
        const float my = means[p * 3 + 1];
        const float mz = means[p * 3 + 2];

        const float tx  = mx * V[0] + my * V[4] + mz * V[8]  + V[12];
        const float ty  = mx * V[1] + my * V[5] + mz * V[9]  + V[13];
        const float tzv = mx * V[2] + my * V[6] + mz * V[10] + V[14];

        const float pp0 = mx * PM[0] + my * PM[4] + mz * PM[8]  + PM[12];
        const float pp1 = mx * PM[1] + my * PM[5] + mz * PM[9]  + PM[13];
        const float pp3 = mx * PM[3] + my * PM[7] + mz * PM[11] + PM[15];
        const float inw = 1.0f / (pp3 + 1e-7f);
        const float ndx = pp0 * inw, ndy = pp1 * inw;

        const float depth = tzv;
        const float fx = (float)Wn / (2.0f * tanx);
        const float fy = (float)Hn / (2.0f * tany);
        const float tz = fmaxf(depth, 1e-6f);
        const float lx = 1.3f * tanx, ly = 1.3f * tany;
        const float txc = fminf(fmaxf(tx / tz, -lx), lx) * tz;
        const float tyc = fminf(fmaxf(ty / tz, -ly), ly) * tz;

        const float J00 = fx / tz, J02 = -fx * txc / (tz * tz);
        const float J11 = fy / tz, J12 = -fy * tyc / (tz * tz);

        float T2r0[3], T2r1[3];
        #pragma unroll
        for (int c = 0; c < 3; c++) {
            T2r0[c] = J00 * V[c * 4 + 0] + J02 * V[c * 4 + 2];
            T2r1[c] = J11 * V[c * 4 + 1] + J12 * V[c * 4 + 2];
        }

        const float4 q = ((const float4*)rots)[p];
        const float qn = rsqrtf(q.x * q.x + q.y * q.y + q.z * q.z + q.w * q.w);
        const float r = q.x * qn, qx = q.y * qn, qy = q.z * qn, qz = q.w * qn;
        float R[3][3];
        R[0][0] = 1.f - 2.f * (qy * qy + qz * qz);
        R[0][1] = 2.f * (qx * qy - r * qz);
        R[0][2] = 2.f * (qx * qz + r * qy);
        R[1][0] = 2.f * (qx * qy + r * qz);
        R[1][1] = 1.f - 2.f * (qx * qx + qz * qz);
        R[1][2] = 2.f * (qy * qz - r * qx);
        R[2][0] = 2.f * (qx * qz - r * qy);
        R[2][1] = 2.f * (qy * qz + r * qx);
        R[2][2] = 1.f - 2.f * (qx * qx + qy * qy);

        const float s0 = scales[p * 3 + 0];
        const float s1 = scales[p * 3 + 1];
        const float s2v = scales[p * 3 + 2];
        const float sq[3] = { s0 * s0, s1 * s1, s2v * s2v };

        float Sig[3][3];
        #pragma unroll
        for (int i = 0; i < 3; i++)
            #pragma unroll
            for (int k = 0; k < 3; k++)
                Sig[i][k] = R[i][0] * sq[0] * R[k][0]
                          + R[i][1] * sq[1] * R[k][1]
                          + R[i][2] * sq[2] * R[k][2];

        float M0[3], M1[3];
        #pragma unroll
        for (int k = 0; k < 3; k++) {
            M0[k] = T2r0[0] * Sig[0][k] + T2r0[1] * Sig[1][k] + T2r0[2] * Sig[2][k];
            M1[k] = T2r1[0] * Sig[0][k] + T2r1[1] * Sig[1][k] + T2r1[2] * Sig[2][k];
        }
        const float cov00 = M0[0] * T2r0[0] + M0[1] * T2r0[1] + M0[2] * T2r0[2];
        const float cov01 = M0[0] * T2r1[0] + M0[1] * T2r1[1] + M0[2] * T2r1[2];
        const float cov11 = M1[0] * T2r1[0] + M1[1] * T2r1[1] + M1[2] * T2r1[2];

        const float a  = cov00 + 0.3f;
        const float cc = cov11 + 0.3f;
        const float bb = cov01;
        const float det = a * cc - bb * bb;
        const bool valid = (det > 0.0f) && (depth > 0.2f);
        const float dets = valid ? det : 1.0f;
        const float conA =  cc / dets;
        const float conB = -bb / dets;
        const float conC =  a  / dets;
        const float mid = 0.5f * (a + cc);
        const float lam = mid + sqrtf(fmaxf(0.1f, mid * mid - det));
        const float radf = valid ? ceilf(3.0f * sqrtf(lam)) : 0.0f;

        const float px = ((ndx + 1.0f) * (float)Wn - 1.0f) * 0.5f;
        const float py = ((ndy + 1.0f) * (float)Hn - 1.0f) * 0.5f;

        const float dx0 = mx - campos[b * 3 + 0];
        const float dy0 = my - campos[b * 3 + 1];
        const float dz0 = mz - campos[b * 3 + 2];
        const float dinv = rsqrtf(dx0 * dx0 + dy0 * dy0 + dz0 * dz0);
        const float x = dx0 * dinv, y = dy0 * dinv, z = dz0 * dinv;
        const float xx = x * x, yy = y * y, zz = z * z;
        const float xy = x * y, yz = y * z, xz = x * z;
        float basis[16];
        basis[0]  = SH_C0;
        basis[1]  = -SH_C1 * y;
        basis[2]  =  SH_C1 * z;
        basis[3]  = -SH_C1 * x;
        basis[4]  = SH_C2_0 * xy;
        basis[5]  = SH_C2_1 * yz;
        basis[6]  = SH_C2_2 * (2.0f * zz - xx - yy);
        basis[7]  = SH_C2_3 * xz;
        basis[8]  = SH_C2_4 * (xx - yy);
        basis[9]  = SH_C3_0 * y * (3.0f * xx - yy);
        basis[10] = SH_C3_1 * xy * z;
        basis[11] = SH_C3_2 * y * (4.0f * zz - xx - yy);
        basis[12] = SH_C3_3 * z * (2.0f * zz - 3.0f * xx - 3.0f * yy);
        basis[13] = SH_C3_4 * x * (4.0f * zz - xx - yy);
        basis[14] = SH_C3_5 * z * (xx - yy);
        basis[15] = SH_C3_6 * x * (xx - 3.0f * yy);

        float shv[48];
        const float4* shp = (const float4*)(sh + p * 48);
        #pragma unroll
        for (int k = 0; k < 12; k++) {
            const float4 v = shp[k];
            shv[k * 4 + 0] = v.x; shv[k * 4 + 1] = v.y;
            shv[k * 4 + 2] = v.z; shv[k * 4 + 3] = v.w;
        }
        float rgb[3];
        #pragma unroll
        for (int c = 0; c < 3; c++) {
            float res = 0.0f;
            #pragma unroll
            for (int k = 0; k < 16; k++)
                res += basis[k] * shv[k * 3 + c];
            rgb[c] = fmaxf(res + 0.5f, 0.0f);
        }

        const float op = valid ? opac[p] : 0.0f;
        const float invdep = 1.0f / tz;
        const float p0   = -logf(255.0f * op);     // op=0 -> +inf
        const float pthr = p0 - 1e-3f;

        float4 aabb;
        if (valid && op > 0.0f) {
            const float ex = sqrtf(fmaxf(0.0f, -2.0f * p0 * a)) + 0.02f;
            const float ey = sqrtf(fmaxf(0.0f, -2.0f * p0 * cc)) + 0.02f;
            aabb = make_float4(px - ex, px + ex, py - ey, py + ey);
        } else {
            aabb = make_float4(1e9f, -1e9f, 1e9f, -1e9f);
        }

        const int gi = b * Pn + p;
        g_a0[gi] = make_float4(px, py, conA, conB);
        g_a1[gi] = make_float4(conC, op, pthr, invdep);
        g_a2[gi] = make_float4(rgb[0], rgb[1], rgb[2], 0.0f);
        g_bb[gi] = aabb;
        g_depth[gi] = depth;
        out[Bn * 4 * NPIX + b * Pn + p] = radf;    // radii tail
    }

    gbar(0);

    // =======================================================================
    // Phase 2: rank sort + scatter. Block handles 16 gaussians of one camera,
    // 8 threads per gaussian scan interleaved (bank-conflict-free).
    // =======================================================================
    {
        const int b = blk >> 6;                   // 64 blocks per camera
        const int gbase = (blk & 63) * 16;
        const float4* dp = (const float4*)(g_depth + b * Pn);
        float4* sd4 = (float4*)sd;
        sd4[tid]       = dp[tid];
        sd4[tid + 128] = dp[tid + 128];
        __syncthreads();

        const int gi  = gbase + (tid >> 3);       // 0..1023 within camera
        const int sub = tid & 7;
        const float di = sd[gi];
        int rank = 0;
        #pragma unroll 16
        for (int i = 0; i < 128; i++) {
            const int j = sub + 8 * i;
            const float dj = sd[j];
            rank += (dj < di) || (dj == di && j < gi);
        }
        rank += __shfl_xor_sync(0xffffffffu, rank, 1);
        rank += __shfl_xor_sync(0xffffffffu, rank, 2);
        rank += __shfl_xor_sync(0xffffffffu, rank, 4);

        if (sub == 0) {
            const int src = b * Pn + gi;
            const int dst = b * Pn + rank;
            g_s0[dst]  = g_a0[src];
            g_s1[dst]  = g_a1[src];
            g_s2[dst]  = g_a2[src];
            g_sbb[dst] = g_bb[src];
        }
    }

    gbar(1);

    // =======================================================================
    // Phase 3: tile binning. One warp per tile (512 warps = 128 blocks x 4).
    // Ballot-compaction preserves depth order.
    // =======================================================================
    {
        const int w    = blk * 4 + (tid >> 5);
        const int lane = tid & 31;
        const int b    = w >> 8;                  // / NT
        const int tile = w & (NT - 1);
        const float tx0 = (float)((tile & (TSX - 1)) * TILE);
        const float ty0 = (float)((tile >> 4) * TILE);
        const float tx1 = tx0 + (float)(TILE - 1);
        const float ty1 = ty0 + (float)(TILE - 1);

        unsigned short* list = g_list + w * Pn;
        int cnt = 0;
        for (int base = 0; base < Pn; base += 32) {
            const int idx = base + lane;
            const float4 bbv = g_sbb[b * Pn + idx];
            const bool hit = (bbv.x <= tx1) && (bbv.y >= tx0) &&
                             (bbv.z <= ty1) && (bbv.w >= ty0);
            const unsigned mask = __ballot_sync(0xffffffffu, hit);
            if (hit) {
                const int pos = cnt + __popc(mask & ((1u << lane) - 1u));
                list[pos] = (unsigned short)idx;
            }
            cnt += __popc(mask);
        }
        if (lane == 0) g_cnt[w] = cnt;
    }

    gbar(2);

    // =======================================================================
    // Phase 4: render. Warp pops tiles from the global queue (load balance).
    // 8x8 tile, 2 pixels per lane: (xl, yl) and (xl, yl+4).
    // =======================================================================
    {
        const int lane = tid & 31;
        const float bg0 = bg[0], bg1 = bg[1], bg2 = bg[2];

        for (;;) {
            int t;
            if (lane == 0) t = (int)atomicAdd(&g_tile_ctr, 1u);
            t = __shfl_sync(0xffffffffu, t, 0);
            if (t >= NTT) break;

            const int b    = t >> 8;
            const int tile = t & (NT - 1);
            const int tx0 = (tile & (TSX - 1)) * TILE;
            const int ty0 = (tile >> 4) * TILE;
            const int xl = lane & 7, yl = lane >> 3;
            const float xf  = (float)(tx0 + xl);
            const float yfA = (float)(ty0 + yl);
            const float yfB = yfA + 4.0f;

            const int cnt = g_cnt[t];
            const unsigned short* list = g_list + t * Pn;
            const float4* s0p = g_s0 + b * Pn;
            const float4* s1p = g_s1 + b * Pn;
            const float4* s2p = g_s2 + b * Pn;

            float TA = 1.0f, TB = 1.0f;
            float cA0 = 0, cA1 = 0, cA2 = 0, ivA = 0;
            float cB0 = 0, cB1 = 0, cB2 = 0, ivB = 0;

            for (int j = 0; j < cnt; j++) {
                const int idx = (int)__ldg(list + j);
                const float4 a0 = __ldg(s0p + idx);
                const float4 a1 = __ldg(s1p + idx);
                const float dx  = xf - a0.x;
                const float dyA = yfA - a0.y;
                const float dyB = yfB - a0.y;
                const float qx  = -0.5f * a0.z * dx * dx;
                const float pA  = qx - 0.5f * a1.x * dyA * dyA - a0.w * dx * dyA;
                const float pB  = qx - 0.5f * a1.x * dyB * dyB - a0.w * dx * dyB;
                const bool hA = (pA >= a1.z) && (pA <= 0.0f);
                const bool hB = (pB >= a1.z) && (pB <= 0.0f);
                if (hA || hB) {
                    const float4 a2 = __ldg(s2p + idx);
                    if (hA) {
                        const float alpha = fminf(0.99f, a1.y * __expf(pA));
                        if (alpha >= (1.0f / 255.0f)) {
                            const float wgt = TA * alpha;
                            cA0 += wgt * a2.x; cA1 += wgt * a2.y;
                            cA2 += wgt * a2.z; ivA += wgt * a1.w;
                            TA *= (1.0f - alpha);
                        }
                    }
                    if (hB) {
                        const float alpha = fminf(0.99f, a1.y * __expf(pB));
                        if (alpha >= (1.0f / 255.0f)) {
                            const float wgt = TB * alpha;
                            cB0 += wgt * a2.x; cB1 += wgt * a2.y;
                            cB2 += wgt * a2.z; ivB += wgt * a1.w;
                            TB *= (1.0f - alpha);
                        }
                    }
                }
                if ((j & 15) == 15) {
                    if (__all_sync(0xffffffffu, TA < 2e-5f && TB < 2e-5f)) break;
                }
            }

            const int xA = tx0 + xl;
            const int yA = ty0 + yl, yB = yA + 4;
            out[((b * 3 + 0) * Hn + yA) * Wn + xA] = cA0 + TA * bg0;
            out[((b * 3 + 1) * Hn + yA) * Wn + xA] = cA1 + TA * bg1;
            out[((b * 3 + 2) * Hn + yA) * Wn + xA] = cA2 + TA * bg2;
            out[Bn * 3 * NPIX + b * NPIX + yA * Wn + xA] = ivA;
            out[((b * 3 + 0) * Hn + yB) * Wn + xA] = cB0 + TB * bg0;
            out[((b * 3 + 1) * Hn + yB) * Wn + xA] = cB1 + TB * bg1;
            out[((b * 3 + 2) * Hn + yB) * Wn + xA] = cB2 + TB * bg2;
            out[Bn * 3 * NPIX + b * NPIX + yB * Wn + xA] = ivB;
        }
    }
}

// ---------------------------------------------------------------------------
extern "C" void kernel_launch(void* const* d_in, const int* in_sizes, int n_in,
                              void* d_out, int out_size)
{
    const float* means  = (const float*)d_in[0];
    const float* opac   = (const float*)d_in[1];
    const float* scales = (const float*)d_in[2];
    const float* rots   = (const float*)d_in[3];
    const float* sh     = (const float*)d_in[4];
    const float* bg     = (const float*)d_in[5];
    const float* viewm  = (const float*)d_in[6];
    const float* projm  = (const float*)d_in[7];
    const float* campos = (const float*)d_in[8];
    const float* tanxs  = (const float*)d_in[9];
    const float* tanys  = (const float*)d_in[10];
    float* out = (float*)d_out;

    fused_kernel<<<NBLK, TPB>>>(means, opac, scales, rots, sh, bg,
                                viewm, projm, campos, tanxs, tanys, out);
}

// round 5
// speedup vs baseline: 1.6113x; 1.6113x over previous
#include <cuda_runtime.h>
#include <cuda_bf16.h>

// Problem constants (fixed by the reference setup)
#define Bn 2
#define Pn 1024
#define Hn 128
#define Wn 128
#define NPIX (Hn * Wn)          // 16384
#define TILE_W 16
#define TILE_H 8
#define TSX (Wn / TILE_W)       // 8
#define TSY (Hn / TILE_H)       // 16
#define NT  (TSX * TSY)         // 128 tiles per camera
#define PRE_TPB 128

// ---------------------------------------------------------------------------
// Scratch (device globals — no allocations allowed). Sorted-order attributes.
// ---------------------------------------------------------------------------
__device__ float4 g_s0[Bn * Pn];    // px, py, conA, conB   (depth-sorted)
__device__ float4 g_s1[Bn * Pn];    // conC, op, pthr(margin), 1/dep
__device__ float4 g_s2[Bn * Pn];    // rgb0, rgb1, rgb2, pad
__device__ float4 g_sbb[Bn * Pn];   // xmin, xmax, ymin, ymax (ellipse AABB)

// SH constants
#define SH_C0 0.28209479177387814f
#define SH_C1 0.4886025119029199f
#define SH_C2_0 1.0925484305920792f
#define SH_C2_1 (-1.0925484305920792f)
#define SH_C2_2 0.31539156525252005f
#define SH_C2_3 (-1.0925484305920792f)
#define SH_C2_4 0.5462742152960396f
#define SH_C3_0 (-0.5900435899266435f)
#define SH_C3_1 2.890611442640554f
#define SH_C3_2 (-0.4570457994644658f)
#define SH_C3_3 0.3731763325901154f
#define SH_C3_4 (-0.4570457994644658f)
#define SH_C3_5 1.445305721320277f
#define SH_C3_6 (-0.5900435899266435f)

// ---------------------------------------------------------------------------
// Kernel 1: preprocess + in-block depth ranking; writes directly to sorted
// slots. grid = (Bn, Pn/PRE_TPB), block = PRE_TPB.
// ---------------------------------------------------------------------------
__global__ __launch_bounds__(PRE_TPB) void preprocess_kernel(
    const float* __restrict__ means,      // (P,3)
    const float* __restrict__ opac,       // (P,1)
    const float* __restrict__ scales,     // (P,3)
    const float* __restrict__ rots,       // (P,4)
    const float* __restrict__ sh,         // (P,16,3)
    const float* __restrict__ viewm,      // (B,4,4) row-major
    const float* __restrict__ projm,      // (B,4,4)
    const float* __restrict__ campos,     // (B,3)
    const float* __restrict__ tanxs,      // (B)
    const float* __restrict__ tanys,      // (B)
    float* __restrict__ out_radii)        // radii tail of output, (B,P)
{
    __shared__ float sd[Pn];              // full per-camera depth table

    const int b = blockIdx.x;
    const int tid = threadIdx.x;
    const int p = blockIdx.y * PRE_TPB + tid;
    const float* V  = viewm + b * 16;
    const float* PM = projm + b * 16;

    // Cooperative depth table: depth(g) = m·V[:,2] + V[14]
    const float v2 = V[2], v6 = V[6], v10 = V[10], v14 = V[14];
    #pragma unroll
    for (int k = 0; k < Pn / PRE_TPB; k++) {
        const int g = tid + k * PRE_TPB;
        sd[g] = means[g * 3 + 0] * v2 + means[g * 3 + 1] * v6
              + means[g * 3 + 2] * v10 + v14;
    }
    __syncthreads();

    // Stable rank of own gaussian: (depth, index) lexicographic == argsort.
    const float di = sd[p];
    int rank = 0;
    const float4* sd4 = (const float4*)sd;
    #pragma unroll 8
    for (int j4 = 0; j4 < Pn / 4; j4++) {
        const float4 v = sd4[j4];
        const int j = j4 * 4;
        rank += (v.x < di) || (v.x == di && (j + 0) < p);
        rank += (v.y < di) || (v.y == di && (j + 1) < p);
        rank += (v.z < di) || (v.z == di && (j + 2) < p);
        rank += (v.w < di) || (v.w == di && (j + 3) < p);
    }

    // ------------------- full preprocess math -------------------
    const float tanx = tanxs[b], tany = tanys[b];
    const float mx = means[p * 3 + 0];
    const float my = means[p * 3 + 1];
    const float mz = means[p * 3 + 2];

    const float tx  = mx * V[0] + my * V[4] + mz * V[8]  + V[12];
    const float ty  = mx * V[1] + my * V[5] + mz * V[9]  + V[13];
    const float depth = di;

    const float pp0 = mx * PM[0] + my * PM[4] + mz * PM[8]  + PM[12];
    const float pp1 = mx * PM[1] + my * PM[5] + mz * PM[9]  + PM[13];
    const float pp3 = mx * PM[3] + my * PM[7] + mz * PM[11] + PM[15];
    const float inw = 1.0f / (pp3 + 1e-7f);
    const float ndx = pp0 * inw, ndy = pp1 * inw;

    const float fx = (float)Wn / (2.0f * tanx);
    const float fy = (float)Hn / (2.0f * tany);
    const float tz = fmaxf(depth, 1e-6f);
    const float lx = 1.3f * tanx, ly = 1.3f * tany;
    const float txc = fminf(fmaxf(tx / tz, -lx), lx) * tz;
    const float tyc = fminf(fmaxf(ty / tz, -ly), ly) * tz;

    const float J00 = fx / tz, J02 = -fx * txc / (tz * tz);
    const float J11 = fy / tz, J12 = -fy * tyc / (tz * tz);

    float T2r0[3], T2r1[3];
    #pragma unroll
    for (int c = 0; c < 3; c++) {
        T2r0[c] = J00 * V[c * 4 + 0] + J02 * V[c * 4 + 2];
        T2r1[c] = J11 * V[c * 4 + 1] + J12 * V[c * 4 + 2];
    }

    const float4 q = ((const float4*)rots)[p];
    const float qn = rsqrtf(q.x * q.x + q.y * q.y + q.z * q.z + q.w * q.w);
    const float r = q.x * qn, qx = q.y * qn, qy = q.z * qn, qz = q.w * qn;
    float R[3][3];
    R[0][0] = 1.f - 2.f * (qy * qy + qz * qz);
    R[0][1] = 2.f * (qx * qy - r * qz);
    R[0][2] = 2.f * (qx * qz + r * qy);
    R[1][0] = 2.f * (qx * qy + r * qz);
    R[1][1] = 1.f - 2.f * (qx * qx + qz * qz);
    R[1][2] = 2.f * (qy * qz - r * qx);
    R[2][0] = 2.f * (qx * qz - r * qy);
    R[2][1] = 2.f * (qy * qz + r * qx);
    R[2][2] = 1.f - 2.f * (qx * qx + qy * qy);

    const float s0v = scales[p * 3 + 0];
    const float s1v = scales[p * 3 + 1];
    const float s2v = scales[p * 3 + 2];
    const float sq[3] = { s0v * s0v, s1v * s1v, s2v * s2v };

    float Sig[3][3];
    #pragma unroll
    for (int i = 0; i < 3; i++)
        #pragma unroll
        for (int k = 0; k < 3; k++)
            Sig[i][k] = R[i][0] * sq[0] * R[k][0]
                      + R[i][1] * sq[1] * R[k][1]
                      + R[i][2] * sq[2] * R[k][2];

    float M0[3], M1[3];
    #pragma unroll
    for (int k = 0; k < 3; k++) {
        M0[k] = T2r0[0] * Sig[0][k] + T2r0[1] * Sig[1][k] + T2r0[2] * Sig[2][k];
        M1[k] = T2r1[0] * Sig[0][k] + T2r1[1] * Sig[1][k] + T2r1[2] * Sig[2][k];
    }
    const float cov00 = M0[0] * T2r0[0] + M0[1] * T2r0[1] + M0[2] * T2r0[2];
    const float cov01 = M0[0] * T2r1[0] + M0[1] * T2r1[1] + M0[2] * T2r1[2];
    const float cov11 = M1[0] * T2r1[0] + M1[1] * T2r1[1] + M1[2] * T2r1[2];

    const float a  = cov00 + 0.3f;
    const float cc = cov11 + 0.3f;
    const float bb = cov01;
    const float det = a * cc - bb * bb;
    const bool valid = (det > 0.0f) && (depth > 0.2f);
    const float dets = valid ? det : 1.0f;
    const float conA =  cc / dets;
    const float conB = -bb / dets;
    const float conC =  a  / dets;
    const float mid = 0.5f * (a + cc);
    const float lam = mid + sqrtf(fmaxf(0.1f, mid * mid - det));
    const float radf = valid ? ceilf(3.0f * sqrtf(lam)) : 0.0f;

    const float px = ((ndx + 1.0f) * (float)Wn - 1.0f) * 0.5f;
    const float py = ((ndy + 1.0f) * (float)Hn - 1.0f) * 0.5f;

    const float dx0 = mx - campos[b * 3 + 0];
    const float dy0 = my - campos[b * 3 + 1];
    const float dz0 = mz - campos[b * 3 + 2];
    const float dinv = rsqrtf(dx0 * dx0 + dy0 * dy0 + dz0 * dz0);
    const float x = dx0 * dinv, y = dy0 * dinv, z = dz0 * dinv;
    const float xx = x * x, yy = y * y, zz = z * z;
    const float xy = x * y, yz = y * z, xz = x * z;
    float basis[16];
    basis[0]  = SH_C0;
    basis[1]  = -SH_C1 * y;
    basis[2]  =  SH_C1 * z;
    basis[3]  = -SH_C1 * x;
    basis[4]  = SH_C2_0 * xy;
    basis[5]  = SH_C2_1 * yz;
    basis[6]  = SH_C2_2 * (2.0f * zz - xx - yy);
    basis[7]  = SH_C2_3 * xz;
    basis[8]  = SH_C2_4 * (xx - yy);
    basis[9]  = SH_C3_0 * y * (3.0f * xx - yy);
    basis[10] = SH_C3_1 * xy * z;
    basis[11] = SH_C3_2 * y * (4.0f * zz - xx - yy);
    basis[12] = SH_C3_3 * z * (2.0f * zz - 3.0f * xx - 3.0f * yy);
    basis[13] = SH_C3_4 * x * (4.0f * zz - xx - yy);
    basis[14] = SH_C3_5 * z * (xx - yy);
    basis[15] = SH_C3_6 * x * (xx - 3.0f * yy);

    float shv[48];
    const float4* shp = (const float4*)(sh + p * 48);
    #pragma unroll
    for (int k = 0; k < 12; k++) {
        const float4 v = shp[k];
        shv[k * 4 + 0] = v.x; shv[k * 4 + 1] = v.y;
        shv[k * 4 + 2] = v.z; shv[k * 4 + 3] = v.w;
    }
    float rgb[3];
    #pragma unroll
    for (int c = 0; c < 3; c++) {
        float res = 0.0f;
        #pragma unroll
        for (int k = 0; k < 16; k++)
            res += basis[k] * shv[k * 3 + c];
        rgb[c] = fmaxf(res + 0.5f, 0.0f);
    }

    const float op = valid ? opac[p] : 0.0f;
    const float invdep = 1.0f / tz;
    const float p0   = -logf(255.0f * op);     // op=0 -> +inf
    const float pthr = p0 - 1e-3f;

    // Conservative AABB of {power >= p0}: |dx|<=sqrt(-2*p0*a), |dy|<=sqrt(-2*p0*c)
    float4 aabb;
    if (valid && op > 0.0f) {
        const float ex = sqrtf(fmaxf(0.0f, -2.0f * p0 * a)) + 0.02f;
        const float ey = sqrtf(fmaxf(0.0f, -2.0f * p0 * cc)) + 0.02f;
        aabb = make_float4(px - ex, px + ex, py - ey, py + ey);
        // NaN px/py propagates -> overlap tests false -> culled
    } else {
        aabb = make_float4(1e9f, -1e9f, 1e9f, -1e9f);
    }

    // Write directly to depth-sorted slot.
    const int dst = b * Pn + rank;
    g_s0[dst]  = make_float4(px, py, conA, conB);
    g_s1[dst]  = make_float4(conC, op, pthr, invdep);
    g_s2[dst]  = make_float4(rgb[0], rgb[1], rgb[2], 0.0f);
    g_sbb[dst] = aabb;
    out_radii[b * Pn + p] = radf;    // radii stay in original order
}

// ---------------------------------------------------------------------------
// Kernel 2: render with fused binning. One block per 16x8 tile (128 threads,
// 1 px/thread). Per 128-gaussian chunk: AABB test + order-preserving block
// compaction -> gather hit attributes to smem -> composite.
// grid = Bn*NT = 256, block = 128.
// ---------------------------------------------------------------------------
__global__ __launch_bounds__(128) void render_kernel(
    const float* __restrict__ bg, float* __restrict__ out)
{
    __shared__ float4 s0[128], s1[128], s2[128];
    __shared__ short  slist[128];
    __shared__ int    wcnt[4];

    const int w = blockIdx.x;
    const int b    = w >> 7;                 // / NT
    const int tile = w & (NT - 1);
    const int tx0 = (tile & (TSX - 1)) * TILE_W;
    const int ty0 = (tile >> 3) * TILE_H;
    const int tid = threadIdx.x;
    const int lane = tid & 31;
    const int wid  = tid >> 5;
    const int x = tx0 + (tid & (TILE_W - 1));
    const int y = ty0 + (tid >> 4);
    const float xf = (float)x, yf = (float)y;

    const float ftx0 = (float)tx0, fty0 = (float)ty0;
    const float ftx1 = ftx0 + (float)(TILE_W - 1);
    const float fty1 = fty0 + (float)(TILE_H - 1);

    const float4* bbp = g_sbb + b * Pn;
    const float4* s0p = g_s0 + b * Pn;
    const float4* s1p = g_s1 + b * Pn;
    const float4* s2p = g_s2 + b * Pn;

    float T = 1.0f, c0 = 0.0f, c1 = 0.0f, c2 = 0.0f, ivd = 0.0f;

    for (int base = 0; base < Pn; base += 128) {
        // ---- fused binning: test + order-preserving compaction ----
        const int gidx = base + tid;
        const float4 bbv = bbp[gidx];
        const bool hit = (bbv.x <= ftx1) && (bbv.y >= ftx0) &&
                         (bbv.z <= fty1) && (bbv.w >= fty0);
        const unsigned mask = __ballot_sync(0xffffffffu, hit);
        if (lane == 0) wcnt[wid] = __popc(mask);
        __syncthreads();
        const int w0 = wcnt[0], w1 = wcnt[1], w2 = wcnt[2], w3 = wcnt[3];
        int wbase = 0;
        if (wid > 0) wbase += w0;
        if (wid > 1) wbase += w1;
        if (wid > 2) wbase += w2;
        const int total = w0 + w1 + w2 + w3;
        __syncthreads();                 // wcnt consumed before next chunk reuse
        if (hit) {
            const int pos = wbase + __popc(mask & ((1u << lane) - 1u));
            slist[pos] = (short)gidx;
        }
        __syncthreads();

        // ---- gather hit attributes into smem ----
        if (tid < total) {
            const int gi = (int)slist[tid];
            s0[tid] = s0p[gi];
            s1[tid] = s1p[gi];
            s2[tid] = s2p[gi];
        }
        __syncthreads();

        // ---- composite (depth order preserved) ----
        for (int j = 0; j < total; j++) {
            const float4 a0 = s0[j];
            const float4 a1 = s1[j];
            const float dx = xf - a0.x;
            const float dy = yf - a0.y;
            const float power = -0.5f * (a0.z * dx * dx + a1.x * dy * dy)
                                - a0.w * dx * dy;
            if (power >= a1.z && power <= 0.0f) {
                const float alpha = fminf(0.99f, a1.y * __expf(power));
                if (alpha >= (1.0f / 255.0f)) {   // exact reference test
                    const float4 a2 = s2[j];
                    const float wgt = T * alpha;
                    c0  += wgt * a2.x;
                    c1  += wgt * a2.y;
                    c2  += wgt * a2.z;
                    ivd += wgt * a1.w;
                    T *= (1.0f - alpha);
                }
            }
        }
        // barrier (buffer reuse) + block-uniform early exit
        if (__syncthreads_and(T < 2e-5f)) break;
    }

    const float bg0 = bg[0], bg1 = bg[1], bg2 = bg[2];
    out[((b * 3 + 0) * Hn + y) * Wn + x] = c0 + T * bg0;
    out[((b * 3 + 1) * Hn + y) * Wn + x] = c1 + T * bg1;
    out[((b * 3 + 2) * Hn + y) * Wn + x] = c2 + T * bg2;
    out[Bn * 3 * NPIX + b * NPIX + y * Wn + x] = ivd;
}

// ---------------------------------------------------------------------------
extern "C" void kernel_launch(void* const* d_in, const int* in_sizes, int n_in,
                              void* d_out, int out_size)
{
    const float* means  = (const float*)d_in[0];
    const float* opac   = (const float*)d_in[1];
    const float* scales = (const float*)d_in[2];
    const float* rots   = (const float*)d_in[3];
    const float* sh     = (const float*)d_in[4];
    const float* bg     = (const float*)d_in[5];
    const float* viewm  = (const float*)d_in[6];
    const float* projm  = (const float*)d_in[7];
    const float* campos = (const float*)d_in[8];
    const float* tanxs  = (const float*)d_in[9];
    const float* tanys  = (const float*)d_in[10];
    float* out = (float*)d_out;

    float* out_radii = out + Bn * 4 * NPIX;   // radii tail at 131072

    dim3 pre_grid(Bn, Pn / PRE_TPB);
    preprocess_kernel<<<pre_grid, PRE_TPB>>>(means, opac, scales, rots, sh,
                                             viewm, projm, campos, tanxs, tanys,
                                             out_radii);
    render_kernel<<<Bn * NT, 128>>>(bg, out);
}

// round 6
// speedup vs baseline: 1.9208x; 1.1921x over previous
#include <cuda_runtime.h>
#include <cuda_bf16.h>

// Problem constants (fixed by the reference setup)
#define Bn 2
#define Pn 1024
#define Hn 128
#define Wn 128
#define NPIX (Hn * Wn)          // 16384
#define TILE_W 16
#define TILE_H 8
#define TSX (Wn / TILE_W)       // 8
#define TSY (Hn / TILE_H)       // 16
#define NT  (TSX * TSY)         // 128 tiles per camera
#define PRE_TPB 64
#define NCHUNK (Pn / 128)       // 8 chunks of 128 in render binning

// ---------------------------------------------------------------------------
// Scratch (device globals — no allocations allowed). Sorted-order attributes.
// ---------------------------------------------------------------------------
__device__ float4 g_s0[Bn * Pn];    // px, py, conA, conB   (depth-sorted)
__device__ float4 g_s1[Bn * Pn];    // conC, op, pthr(margin), 1/dep
__device__ float4 g_s2[Bn * Pn];    // rgb0, rgb1, rgb2, pad
__device__ float4 g_sbb[Bn * Pn];   // xmin, xmax, ymin, ymax (ellipse AABB)

// SH constants
#define SH_C0 0.28209479177387814f
#define SH_C1 0.4886025119029199f
#define SH_C2_0 1.0925484305920792f
#define SH_C2_1 (-1.0925484305920792f)
#define SH_C2_2 0.31539156525252005f
#define SH_C2_3 (-1.0925484305920792f)
#define SH_C2_4 0.5462742152960396f
#define SH_C3_0 (-0.5900435899266435f)
#define SH_C3_1 2.890611442640554f
#define SH_C3_2 (-0.4570457994644658f)
#define SH_C3_3 0.3731763325901154f
#define SH_C3_4 (-0.4570457994644658f)
#define SH_C3_5 1.445305721320277f
#define SH_C3_6 (-0.5900435899266435f)

// ---------------------------------------------------------------------------
// Kernel 1: preprocess + in-block depth ranking; writes directly to sorted
// slots. grid = (Bn, Pn/PRE_TPB) = (2,16), block = 64.
// ---------------------------------------------------------------------------
__global__ __launch_bounds__(PRE_TPB) void preprocess_kernel(
    const float* __restrict__ means,      // (P,3)
    const float* __restrict__ opac,       // (P,1)
    const float* __restrict__ scales,     // (P,3)
    const float* __restrict__ rots,       // (P,4)
    const float* __restrict__ sh,         // (P,16,3)
    const float* __restrict__ viewm,      // (B,4,4) row-major
    const float* __restrict__ projm,      // (B,4,4)
    const float* __restrict__ campos,     // (B,3)
    const float* __restrict__ tanxs,      // (B)
    const float* __restrict__ tanys,      // (B)
    float* __restrict__ out_radii)        // radii tail of output, (B,P)
{
    __shared__ float sd[Pn];              // full per-camera depth table

    const int b = blockIdx.x;
    const int tid = threadIdx.x;
    const int p = blockIdx.y * PRE_TPB + tid;
    const float* V  = viewm + b * 16;
    const float* PM = projm + b * 16;

    // Cooperative depth table via float4 loads: thread t covers gaussians
    // [16t, 16t+16) = floats [48t, 48t+48) = 12 float4.
    const float v2 = V[2], v6 = V[6], v10 = V[10], v14 = V[14];
    {
        const float4* m4 = (const float4*)means;
        float f[48];
        #pragma unroll
        for (int k = 0; k < 12; k++) {
            const float4 v = m4[tid * 12 + k];
            f[k * 4 + 0] = v.x; f[k * 4 + 1] = v.y;
            f[k * 4 + 2] = v.z; f[k * 4 + 3] = v.w;
        }
        #pragma unroll
        for (int i = 0; i < 16; i++)
            sd[tid * 16 + i] = f[3 * i] * v2 + f[3 * i + 1] * v6
                             + f[3 * i + 2] * v10 + v14;
    }
    __syncthreads();

    // Stable rank of own gaussian: (depth, index) lexicographic == argsort.
    const float di = sd[p];
    int rank = 0;
    const float4* sd4 = (const float4*)sd;
    #pragma unroll 8
    for (int j4 = 0; j4 < Pn / 4; j4++) {
        const float4 v = sd4[j4];
        const int j = j4 * 4;
        rank += (v.x < di) || (v.x == di && (j + 0) < p);
        rank += (v.y < di) || (v.y == di && (j + 1) < p);
        rank += (v.z < di) || (v.z == di && (j + 2) < p);
        rank += (v.w < di) || (v.w == di && (j + 3) < p);
    }

    // ------------------- full preprocess math -------------------
    const float tanx = tanxs[b], tany = tanys[b];
    const float mx = means[p * 3 + 0];
    const float my = means[p * 3 + 1];
    const float mz = means[p * 3 + 2];

    const float tx  = mx * V[0] + my * V[4] + mz * V[8]  + V[12];
    const float ty  = mx * V[1] + my * V[5] + mz * V[9]  + V[13];
    const float depth = di;

    const float pp0 = mx * PM[0] + my * PM[4] + mz * PM[8]  + PM[12];
    const float pp1 = mx * PM[1] + my * PM[5] + mz * PM[9]  + PM[13];
    const float pp3 = mx * PM[3] + my * PM[7] + mz * PM[11] + PM[15];
    const float inw = 1.0f / (pp3 + 1e-7f);
    const float ndx = pp0 * inw, ndy = pp1 * inw;

    const float fx = (float)Wn / (2.0f * tanx);
    const float fy = (float)Hn / (2.0f * tany);
    const float tz = fmaxf(depth, 1e-6f);
    const float lx = 1.3f * tanx, ly = 1.3f * tany;
    const float txc = fminf(fmaxf(tx / tz, -lx), lx) * tz;
    const float tyc = fminf(fmaxf(ty / tz, -ly), ly) * tz;

    const float J00 = fx / tz, J02 = -fx * txc / (tz * tz);
    const float J11 = fy / tz, J12 = -fy * tyc / (tz * tz);

    float T2r0[3], T2r1[3];
    #pragma unroll
    for (int c = 0; c < 3; c++) {
        T2r0[c] = J00 * V[c * 4 + 0] + J02 * V[c * 4 + 2];
        T2r1[c] = J11 * V[c * 4 + 1] + J12 * V[c * 4 + 2];
    }

    const float4 q = ((const float4*)rots)[p];
    const float qn = rsqrtf(q.x * q.x + q.y * q.y + q.z * q.z + q.w * q.w);
    const float r = q.x * qn, qx = q.y * qn, qy = q.z * qn, qz = q.w * qn;
    float R[3][3];
    R[0][0] = 1.f - 2.f * (qy * qy + qz * qz);
    R[0][1] = 2.f * (qx * qy - r * qz);
    R[0][2] = 2.f * (qx * qz + r * qy);
    R[1][0] = 2.f * (qx * qy + r * qz);
    R[1][1] = 1.f - 2.f * (qx * qx + qz * qz);
    R[1][2] = 2.f * (qy * qz - r * qx);
    R[2][0] = 2.f * (qx * qz - r * qy);
    R[2][1] = 2.f * (qy * qz + r * qx);
    R[2][2] = 1.f - 2.f * (qx * qx + qy * qy);

    const float s0v = scales[p * 3 + 0];
    const float s1v = scales[p * 3 + 1];
    const float s2v = scales[p * 3 + 2];
    const float sq[3] = { s0v * s0v, s1v * s1v, s2v * s2v };

    float Sig[3][3];
    #pragma unroll
    for (int i = 0; i < 3; i++)
        #pragma unroll
        for (int k = 0; k < 3; k++)
            Sig[i][k] = R[i][0] * sq[0] * R[k][0]
                      + R[i][1] * sq[1] * R[k][1]
                      + R[i][2] * sq[2] * R[k][2];

    float M0[3], M1[3];
    #pragma unroll
    for (int k = 0; k < 3; k++) {
        M0[k] = T2r0[0] * Sig[0][k] + T2r0[1] * Sig[1][k] + T2r0[2] * Sig[2][k];
        M1[k] = T2r1[0] * Sig[0][k] + T2r1[1] * Sig[1][k] + T2r1[2] * Sig[2][k];
    }
    const float cov00 = M0[0] * T2r0[0] + M0[1] * T2r0[1] + M0[2] * T2r0[2];
    const float cov01 = M0[0] * T2r1[0] + M0[1] * T2r1[1] + M0[2] * T2r1[2];
    const float cov11 = M1[0] * T2r1[0] + M1[1] * T2r1[1] + M1[2] * T2r1[2];

    const float a  = cov00 + 0.3f;
    const float cc = cov11 + 0.3f;
    const float bb = cov01;
    const float det = a * cc - bb * bb;
    const bool valid = (det > 0.0f) && (depth > 0.2f);
    const float dets = valid ? det : 1.0f;
    const float conA =  cc / dets;
    const float conB = -bb / dets;
    const float conC =  a  / dets;
    const float mid = 0.5f * (a + cc);
    const float lam = mid + sqrtf(fmaxf(0.1f, mid * mid - det));
    const float radf = valid ? ceilf(3.0f * sqrtf(lam)) : 0.0f;

    const float px = ((ndx + 1.0f) * (float)Wn - 1.0f) * 0.5f;
    const float py = ((ndy + 1.0f) * (float)Hn - 1.0f) * 0.5f;

    const float dx0 = mx - campos[b * 3 + 0];
    const float dy0 = my - campos[b * 3 + 1];
    const float dz0 = mz - campos[b * 3 + 2];
    const float dinv = rsqrtf(dx0 * dx0 + dy0 * dy0 + dz0 * dz0);
    const float x = dx0 * dinv, y = dy0 * dinv, z = dz0 * dinv;
    const float xx = x * x, yy = y * y, zz = z * z;
    const float xy = x * y, yz = y * z, xz = x * z;
    float basis[16];
    basis[0]  = SH_C0;
    basis[1]  = -SH_C1 * y;
    basis[2]  =  SH_C1 * z;
    basis[3]  = -SH_C1 * x;
    basis[4]  = SH_C2_0 * xy;
    basis[5]  = SH_C2_1 * yz;
    basis[6]  = SH_C2_2 * (2.0f * zz - xx - yy);
    basis[7]  = SH_C2_3 * xz;
    basis[8]  = SH_C2_4 * (xx - yy);
    basis[9]  = SH_C3_0 * y * (3.0f * xx - yy);
    basis[10] = SH_C3_1 * xy * z;
    basis[11] = SH_C3_2 * y * (4.0f * zz - xx - yy);
    basis[12] = SH_C3_3 * z * (2.0f * zz - 3.0f * xx - 3.0f * yy);
    basis[13] = SH_C3_4 * x * (4.0f * zz - xx - yy);
    basis[14] = SH_C3_5 * z * (xx - yy);
    basis[15] = SH_C3_6 * x * (xx - 3.0f * yy);

    float shv[48];
    const float4* shp = (const float4*)(sh + p * 48);
    #pragma unroll
    for (int k = 0; k < 12; k++) {
        const float4 v = shp[k];
        shv[k * 4 + 0] = v.x; shv[k * 4 + 1] = v.y;
        shv[k * 4 + 2] = v.z; shv[k * 4 + 3] = v.w;
    }
    float rgb[3];
    #pragma unroll
    for (int c = 0; c < 3; c++) {
        float res = 0.0f;
        #pragma unroll
        for (int k = 0; k < 16; k++)
            res += basis[k] * shv[k * 3 + c];
        rgb[c] = fmaxf(res + 0.5f, 0.0f);
    }

    const float op = valid ? opac[p] : 0.0f;
    const float invdep = 1.0f / tz;
    const float p0   = -logf(255.0f * op);     // op=0 -> +inf
    const float pthr = p0 - 1e-3f;

    // Conservative AABB of {power >= p0}: |dx|<=sqrt(-2*p0*a), |dy|<=sqrt(-2*p0*c)
    float4 aabb;
    if (valid && op > 0.0f) {
        const float ex = sqrtf(fmaxf(0.0f, -2.0f * p0 * a)) + 0.02f;
        const float ey = sqrtf(fmaxf(0.0f, -2.0f * p0 * cc)) + 0.02f;
        aabb = make_float4(px - ex, px + ex, py - ey, py + ey);
        // NaN px/py propagates -> overlap tests false -> culled
    } else {
        aabb = make_float4(1e9f, -1e9f, 1e9f, -1e9f);
    }

    // Write directly to depth-sorted slot.
    const int dst = b * Pn + rank;
    g_s0[dst]  = make_float4(px, py, conA, conB);
    g_s1[dst]  = make_float4(conC, op, pthr, invdep);
    g_s2[dst]  = make_float4(rgb[0], rgb[1], rgb[2], 0.0f);
    g_sbb[dst] = aabb;
    out_radii[b * Pn + p] = radf;    // radii stay in original order
}

// ---------------------------------------------------------------------------
// Kernel 2: render with batched-ballot binning. One block per 16x8 tile
// (128 threads, 1 px/thread). All 8 AABB chunks tested up front, masks parked
// in smem, ONE prefix pass builds the whole depth-ordered hit list, then
// gather+composite in <=128-entry chunks.  grid = Bn*NT = 256, block = 128.
// ---------------------------------------------------------------------------
__global__ __launch_bounds__(128) void render_kernel(
    const float* __restrict__ bg, float* __restrict__ out)
{
    __shared__ unsigned smask[NCHUNK][4];
    __shared__ short    slist[Pn];
    __shared__ float4   s0[128], s1[128], s2[128];

    const int w = blockIdx.x;
    const int b    = w >> 7;                 // / NT
    const int tile = w & (NT - 1);
    const int tx0 = (tile & (TSX - 1)) * TILE_W;
    const int ty0 = (tile >> 3) * TILE_H;
    const int tid = threadIdx.x;
    const int lane = tid & 31;
    const int wid  = tid >> 5;
    const int x = tx0 + (tid & (TILE_W - 1));
    const int y = ty0 + (tid >> 4);
    const float xf = (float)x, yf = (float)y;

    const float ftx0 = (float)tx0, fty0 = (float)ty0;
    const float ftx1 = ftx0 + (float)(TILE_W - 1);
    const float fty1 = fty0 + (float)(TILE_H - 1);

    const float4* bbp = g_sbb + b * Pn;
    const float4* s0p = g_s0 + b * Pn;
    const float4* s1p = g_s1 + b * Pn;
    const float4* s2p = g_s2 + b * Pn;

    // ---- Phase A: all AABB tests, no barriers ----
    unsigned hitbits = 0;
    #pragma unroll
    for (int c = 0; c < NCHUNK; c++) {
        const float4 bbv = bbp[c * 128 + tid];
        const bool h = (bbv.x <= ftx1) && (bbv.y >= ftx0) &&
                       (bbv.z <= fty1) && (bbv.w >= fty0);
        const unsigned m = __ballot_sync(0xffffffffu, h);
        if (h) hitbits |= (1u << c);
        if (lane == 0) smask[c][wid] = m;
    }
    __syncthreads();

    // ---- Phase B: global order-preserving positions from the mask table ----
    int total = 0;
    {
        const unsigned ltmask = (1u << lane) - 1u;
        #pragma unroll
        for (int c = 0; c < NCHUNK; c++) {
            const unsigned m0 = smask[c][0], m1 = smask[c][1];
            const unsigned m2 = smask[c][2], m3 = smask[c][3];
            if (hitbits & (1u << c)) {
                int pos = total;
                if (wid > 0) pos += __popc(m0);
                if (wid > 1) pos += __popc(m1);
                if (wid > 2) pos += __popc(m2);
                pos += __popc(smask[c][wid] & ltmask);
                slist[pos] = (short)(c * 128 + tid);
            }
            total += __popc(m0) + __popc(m1) + __popc(m2) + __popc(m3);
        }
    }
    __syncthreads();

    // ---- Phase C: gather + composite in chunks of 128 ----
    float T = 1.0f, c0 = 0.0f, c1 = 0.0f, c2 = 0.0f, ivd = 0.0f;

    for (int lb = 0; lb < total; lb += 128) {
        if (lb + tid < total) {
            const int gi = (int)slist[lb + tid];
            s0[tid] = s0p[gi];
            s1[tid] = s1p[gi];
            s2[tid] = s2p[gi];
        }
        __syncthreads();

        const int m = min(128, total - lb);
        for (int j = 0; j < m; j++) {
            const float4 a0 = s0[j];
            const float4 a1 = s1[j];
            const float dx = xf - a0.x;
            const float dy = yf - a0.y;
            const float power = -0.5f * (a0.z * dx * dx + a1.x * dy * dy)
                                - a0.w * dx * dy;
            if (power >= a1.z && power <= 0.0f) {
                const float alpha = fminf(0.99f, a1.y * __expf(power));
                if (alpha >= (1.0f / 255.0f)) {   // exact reference test
                    const float4 a2 = s2[j];
                    const float wgt = T * alpha;
                    c0  += wgt * a2.x;
                    c1  += wgt * a2.y;
                    c2  += wgt * a2.z;
                    ivd += wgt * a1.w;
                    T *= (1.0f - alpha);
                }
            }
        }
        // barrier (buffer reuse) + block-uniform early exit
        if (__syncthreads_and(T < 2e-5f)) break;
    }

    const float bg0 = bg[0], bg1 = bg[1], bg2 = bg[2];
    out[((b * 3 + 0) * Hn + y) * Wn + x] = c0 + T * bg0;
    out[((b * 3 + 1) * Hn + y) * Wn + x] = c1 + T * bg1;
    out[((b * 3 + 2) * Hn + y) * Wn + x] = c2 + T * bg2;
    out[Bn * 3 * NPIX + b * NPIX + y * Wn + x] = ivd;
}

// ---------------------------------------------------------------------------
extern "C" void kernel_launch(void* const* d_in, const int* in_sizes, int n_in,
                              void* d_out, int out_size)
{
    const float* means  = (const float*)d_in[0];
    const float* opac   = (const float*)d_in[1];
    const float* scales = (const float*)d_in[2];
    const float* rots   = (const float*)d_in[3];
    const float* sh     = (const float*)d_in[4];
    const float* bg     = (const float*)d_in[5];
    const float* viewm  = (const float*)d_in[6];
    const float* projm  = (const float*)d_in[7];
    const float* campos = (const float*)d_in[8];
    const float* tanxs  = (const float*)d_in[9];
    const float* tanys  = (const float*)d_in[10];
    float* out = (float*)d_out;

    float* out_radii = out + Bn * 4 * NPIX;   // radii tail at 131072

    dim3 pre_grid(Bn, Pn / PRE_TPB);
    preprocess_kernel<<<pre_grid, PRE_TPB>>>(means, opac, scales, rots, sh,
                                             viewm, projm, campos, tanxs, tanys,
                                             out_radii);
    render_kernel<<<Bn * NT, 128>>>(bg, out);
}